// round 3
// baseline (speedup 1.0000x reference)
#include <cuda_runtime.h>
#include <math.h>

// ---------------------------------------------------------------------------
// VQ-VAE forward.  B=16, L=156, P=8, H=W=128, codebook 512x8.
// R3: cp.async double-buffered staging + pre-packed paired weights.
// ---------------------------------------------------------------------------

#define BATCH 16
#define HW    16384   // 128*128

typedef unsigned long long u64;

__device__ __forceinline__ u64 pack2(float lo, float hi) {
    u64 r; asm("mov.b64 %0, {%1, %2};" : "=l"(r) : "f"(lo), "f"(hi)); return r;
}
__device__ __forceinline__ void fma2(u64 &d, u64 a, u64 b) {
    asm("fma.rn.f32x2 %0, %1, %2, %0;" : "+l"(d) : "l"(a), "l"(b));
}
__device__ __forceinline__ float2 unpk(u64 v) {
    float lo, hi; asm("mov.b64 {%0, %1}, %2;" : "=f"(lo), "=f"(hi) : "l"(v));
    return make_float2(lo, hi);
}
__device__ __forceinline__ void cp16(unsigned dst, const void* src, int srcsize) {
    asm volatile("cp.async.cg.shared.global [%0], [%1], 16, %2;"
                 :: "r"(dst), "l"(src), "r"(srcsize) : "memory");
}

// Static device scratch (allocation-free rule).
__device__ float g_z1[BATCH * 128 * HW];
__device__ float g_z2[BATCH *  64 * HW];
__device__ float g_z3[BATCH *   8 * HW];
__device__ float g_q [BATCH *   8 * HW];
__device__ float g_y1[BATCH *  64 * HW];
__device__ float g_y2[BATCH * 128 * HW];
// packed paired weights: [chunk][cp][kc*9+tap] as u64 {w[2cp], w[2cp+1]}
__device__ u64 g_pw_e1[20 * 64 * 72];
__device__ u64 g_pw_e2[16 * 32 * 72];
__device__ u64 g_pw_e3[ 8 *  8 * 72];
__device__ u64 g_pw_d1[ 1 * 32 * 72];
__device__ u64 g_pw_d2[ 8 * 64 * 72];
__device__ u64 g_pw_d3[16 * 80 * 72];
__device__ double g_part[256];

// ---------------------------------------------------------------------------
// Pack weights into [chunk][cp][kc*9+tap] u64 pairs.  transposed=1 handles
// ConvTranspose (in,out,kh,kw) with spatial flip: tap' = 8 - tap.
// ---------------------------------------------------------------------------
__global__ void pack_weights(const float* __restrict__ w, u64* __restrict__ pw,
                             int CIN, int COUT, int CP_PAD, int transposed) {
    int idx = blockIdx.x * 256 + threadIdx.x;
    int CHUNKS = (CIN + 7) / 8;
    int total = CHUNKS * CP_PAD * 72;
    if (idx >= total) return;
    int chunk = idx / (CP_PAD * 72);
    int rem   = idx % (CP_PAD * 72);
    int cp    = rem / 72;
    int rem2  = rem % 72;
    int kc    = rem2 / 9;
    int tap   = rem2 % 9;
    int ci    = chunk * 8 + kc;
    int co0 = 2 * cp, co1 = 2 * cp + 1;
    float v0 = 0.f, v1 = 0.f;
    if (ci < CIN) {
        if (transposed) {
            if (co0 < COUT) v0 = w[((size_t)ci * COUT + co0) * 9 + (8 - tap)];
            if (co1 < COUT) v1 = w[((size_t)ci * COUT + co1) * 9 + (8 - tap)];
        } else {
            if (co0 < COUT) v0 = w[((size_t)co0 * CIN + ci) * 9 + tap];
            if (co1 < COUT) v1 = w[((size_t)co1 * CIN + ci) * 9 + tap];
        }
    }
    pw[idx] = pack2(v0, v1);
}

__device__ __forceinline__ float apply_act(float v, int ACT) {
    if (ACT == 1) return fmaxf(v, 0.f);
    if (ACT == 2) return 1.f / (1.f + __expf(-v));
    return v;
}

// ---------------------------------------------------------------------------
// Packed-f32x2 3x3 same-conv, cp.async double-buffered.
// Block = (n, row-pair, MT output channels at CO_OFF + by*MT).
// 256 thr: lane -> 4 consecutive px (p0=4*lane), cg -> co-pair group.
// smem input row layout: x[gc] at float index gc+8; halos (idx 7, 136) are
// always zero (pre-zeroed once, never overwritten).
// ---------------------------------------------------------------------------
template<int CIN, int COUT, int MT, int ACT, int CO_OFF, int CP_PAD>
__global__ __launch_bounds__(256, 2)
void conv3x3p(const float* __restrict__ in, const u64* __restrict__ pw,
              const float* __restrict__ bias, float* __restrict__ out) {
    constexpr int KC     = 8;
    constexpr int NCP    = MT / 16;           // co-pairs per thread
    constexpr int NCPG   = MT / 2;            // co-pairs per block
    constexpr int CHUNKS = (CIN + KC - 1) / KC;
    constexpr int ROWSTR = 140;               // floats per staged row
    constexpr int INBUF  = KC * 4 * ROWSTR;   // floats per input buffer

    extern __shared__ char smem[];
    float* s_in = (float*)smem;                           // [2][KC][4][ROWSTR]
    u64*   s_w  = (u64*)(smem + 2 * INBUF * 4);           // [2][NCPG][72]

    const int n       = blockIdx.z;
    const int h0      = blockIdx.x * 2;
    const int co_base = CO_OFF + blockIdx.y * MT;
    const int cp_base = co_base / 2;
    const int tid     = threadIdx.x;
    const int lane    = tid & 31;
    const int cg      = tid >> 5;
    const int p0      = lane * 4;

    const float* inN = in + (size_t)n * CIN * HW;

    // zero halo columns in both buffers (never overwritten by cp.async)
    for (int i = tid; i < 2 * KC * 4; i += 256) {
        int b  = i >> 5;
        int kc = (i >> 2) & 7;
        int r  = i & 3;
        float* row = s_in + ((size_t)b * KC * 4 + kc * 4 + r) * ROWSTR;
        row[7] = 0.f; row[136] = 0.f;
    }

    u64 acc[2][NCP][4];
#pragma unroll
    for (int r = 0; r < 2; r++)
#pragma unroll
        for (int c = 0; c < NCP; c++)
#pragma unroll
            for (int k = 0; k < 4; k++) acc[r][c][k] = 0ull;

    // ---- async stage of one chunk into buffer b
    auto issue = [&](int chunk, int b) {
        // input: KC ch x 4 rows x 32 x 16B
        for (int s4 = tid; s4 < KC * 4 * 32; s4 += 256) {
            int kc = s4 >> 7;
            int r  = (s4 >> 5) & 3;
            int s  = s4 & 31;
            int ci = chunk * KC + kc;
            int gh = h0 - 1 + r;
            bool ok = (ci < CIN) && (gh >= 0) && (gh < 128);
            const float* src = inN + (size_t)(ok ? ci : 0) * HW + (ok ? gh : 0) * 128 + s * 4;
            float* dst = s_in + ((size_t)b * KC * 4 + kc * 4 + r) * ROWSTR + 8 + s * 4;
            cp16((unsigned)__cvta_generic_to_shared(dst), src, ok ? 16 : 0);
        }
        // weights: NCPG*72 u64 contiguous
        const u64* wsrc = pw + ((size_t)chunk * CP_PAD + cp_base) * 72;
        u64* wdst = s_w + (size_t)b * NCPG * 72;
        for (int s = tid; s < NCPG * 36; s += 256) {
            cp16((unsigned)__cvta_generic_to_shared((char*)wdst + s * 16),
                 (const char*)wsrc + s * 16, 16);
        }
        asm volatile("cp.async.commit_group;" ::: "memory");
    };

    issue(0, 0);

    for (int c = 0; c < CHUNKS; c++) {
        asm volatile("cp.async.wait_group 0;" ::: "memory");
        __syncthreads();
        if (c + 1 < CHUNKS) issue(c + 1, (c + 1) & 1);

        const int b = c & 1;
        const float* sib = s_in + (size_t)b * INBUF;
        const u64*   swb = s_w + (size_t)b * NCPG * 72;

        for (int kc = 0; kc < KC; kc++) {
#pragma unroll
            for (int dh = 0; dh < 3; dh++) {
                u64 dup[2][6];
#pragma unroll
                for (int rr = 0; rr < 2; rr++) {
                    const float* row = sib + (kc * 4 + dh + rr) * ROWSTR;
                    float4 a  = *(const float4*)(row + p0 + 4);
                    float4 bb = *(const float4*)(row + p0 + 8);
                    float4 cc = *(const float4*)(row + p0 + 12);
                    dup[rr][0] = pack2(a.w,  a.w);
                    dup[rr][1] = pack2(bb.x, bb.x);
                    dup[rr][2] = pack2(bb.y, bb.y);
                    dup[rr][3] = pack2(bb.z, bb.z);
                    dup[rr][4] = pack2(bb.w, bb.w);
                    dup[rr][5] = pack2(cc.x, cc.x);
                }
#pragma unroll
                for (int dw = 0; dw < 3; dw++) {
#pragma unroll
                    for (int cp = 0; cp < NCP; cp++) {
                        u64 w = swb[(cg * NCP + cp) * 72 + kc * 9 + dh * 3 + dw];
#pragma unroll
                        for (int rr = 0; rr < 2; rr++)
#pragma unroll
                            for (int k = 0; k < 4; k++)
                                fma2(acc[rr][cp][k], w, dup[rr][k + dw]);
                    }
                }
            }
        }
        // next iteration's wait+sync protects buffer reuse
    }

    // ---- epilogue
#pragma unroll
    for (int orow = 0; orow < 2; orow++) {
#pragma unroll
        for (int cp = 0; cp < NCP; cp++) {
            int co0 = co_base + 2 * (cg * NCP + cp);
            float2 r0 = unpk(acc[orow][cp][0]);
            float2 r1 = unpk(acc[orow][cp][1]);
            float2 r2 = unpk(acc[orow][cp][2]);
            float2 r3 = unpk(acc[orow][cp][3]);
            size_t rowoff = (size_t)(h0 + orow) * 128 + p0;
            if (co0 < COUT) {
                float b = bias[co0];
                float4 o;
                o.x = apply_act(r0.x + b, ACT);
                o.y = apply_act(r1.x + b, ACT);
                o.z = apply_act(r2.x + b, ACT);
                o.w = apply_act(r3.x + b, ACT);
                *(float4*)&out[((size_t)n * COUT + co0) * HW + rowoff] = o;
            }
            if (co0 + 1 < COUT) {
                float b = bias[co0 + 1];
                float4 o;
                o.x = apply_act(r0.y + b, ACT);
                o.y = apply_act(r1.y + b, ACT);
                o.z = apply_act(r2.y + b, ACT);
                o.w = apply_act(r3.y + b, ACT);
                *(float4*)&out[((size_t)n * COUT + (co0 + 1)) * HW + rowoff] = o;
            }
        }
    }
}

// ---------------------------------------------------------------------------
// Vector quantizer (groups of 8 along W, torch .view semantics).
// ---------------------------------------------------------------------------
__global__ __launch_bounds__(256)
void vq_kernel(const float* __restrict__ z, const float* __restrict__ emb,
               float* __restrict__ q, double* __restrict__ part) {
    __shared__ float  s_e[512 * 8];
    __shared__ float  s_hn[512];
    __shared__ double s_red[256];

    const int tid = threadIdx.x;
    for (int i = tid; i < 4096; i += 256) s_e[i] = emb[i];
    __syncthreads();
    for (int k = tid; k < 512; k += 256) {
        float s = 0.f;
#pragma unroll
        for (int j = 0; j < 8; j++) { float e = s_e[k * 8 + j]; s += e * e; }
        s_hn[k] = 0.5f * s;
    }
    __syncthreads();

    const int base = blockIdx.x * 1024 + tid;
    float v[4][8];
#pragma unroll
    for (int u = 0; u < 4; u++) {
        int vi = base + u * 256;
        float4 a = ((const float4*)z)[vi * 2];
        float4 b = ((const float4*)z)[vi * 2 + 1];
        v[u][0] = a.x; v[u][1] = a.y; v[u][2] = a.z; v[u][3] = a.w;
        v[u][4] = b.x; v[u][5] = b.y; v[u][6] = b.z; v[u][7] = b.w;
    }

    float best[4] = {3.4e38f, 3.4e38f, 3.4e38f, 3.4e38f};
    int   bk[4]   = {0, 0, 0, 0};
    for (int k = 0; k < 512; k++) {
        float e0 = s_e[k * 8 + 0], e1 = s_e[k * 8 + 1], e2 = s_e[k * 8 + 2], e3 = s_e[k * 8 + 3];
        float e4 = s_e[k * 8 + 4], e5 = s_e[k * 8 + 5], e6 = s_e[k * 8 + 6], e7 = s_e[k * 8 + 7];
        float hn = s_hn[k];
#pragma unroll
        for (int u = 0; u < 4; u++) {
            float dot = e0 * v[u][0] + e1 * v[u][1] + e2 * v[u][2] + e3 * v[u][3]
                      + e4 * v[u][4] + e5 * v[u][5] + e6 * v[u][6] + e7 * v[u][7];
            float sc = hn - dot;
            if (sc < best[u]) { best[u] = sc; bk[u] = k; }
        }
    }

    float sq = 0.f;
#pragma unroll
    for (int u = 0; u < 4; u++) {
        int vi = base + u * 256;
        int kb = bk[u];
        float4 o1, o2;
        o1.x = s_e[kb * 8 + 0]; o1.y = s_e[kb * 8 + 1];
        o1.z = s_e[kb * 8 + 2]; o1.w = s_e[kb * 8 + 3];
        o2.x = s_e[kb * 8 + 4]; o2.y = s_e[kb * 8 + 5];
        o2.z = s_e[kb * 8 + 6]; o2.w = s_e[kb * 8 + 7];
#pragma unroll
        for (int j = 0; j < 8; j++) {
            float d = s_e[kb * 8 + j] - v[u][j];
            sq += d * d;
        }
        ((float4*)q)[vi * 2]     = o1;
        ((float4*)q)[vi * 2 + 1] = o2;
    }

    s_red[tid] = (double)sq;
    __syncthreads();
    for (int o = 128; o > 0; o >>= 1) {
        if (tid < o) s_red[tid] += s_red[tid + o];
        __syncthreads();
    }
    if (tid == 0) part[blockIdx.x] = s_red[0];
}

__global__ void finalize_loss(const double* __restrict__ part, float* __restrict__ outp) {
    __shared__ double s[256];
    int tid = threadIdx.x;
    s[tid] = part[tid];
    __syncthreads();
    for (int o = 128; o > 0; o >>= 1) {
        if (tid < o) s[tid] += s[tid + o];
        __syncthreads();
    }
    if (tid == 0) *outp = (float)(1.25 * s[0] / 2097152.0);
}

// ---------------------------------------------------------------------------
extern "C" void kernel_launch(void* const* d_in, const int* in_sizes, int n_in,
                              void* d_out, int out_size) {
    (void)in_sizes; (void)n_in;
    const float* x   = (const float*)d_in[0];
    const float* e1w = (const float*)d_in[1];
    const float* e1b = (const float*)d_in[2];
    const float* e2w = (const float*)d_in[3];
    const float* e2b = (const float*)d_in[4];
    const float* e3w = (const float*)d_in[5];
    const float* e3b = (const float*)d_in[6];
    const float* emb = (const float*)d_in[7];
    const float* d1w = (const float*)d_in[8];
    const float* d1b = (const float*)d_in[9];
    const float* d2w = (const float*)d_in[10];
    const float* d2b = (const float*)d_in[11];
    const float* d3w = (const float*)d_in[12];
    const float* d3b = (const float*)d_in[13];
    float* out = (float*)d_out;

    void *z1, *z2, *z3, *q, *y1, *y2, *part;
    void *pw1, *pw2, *pw3, *pw4, *pw5, *pw6;
    cudaGetSymbolAddress(&z1,  g_z1);
    cudaGetSymbolAddress(&z2,  g_z2);
    cudaGetSymbolAddress(&z3,  g_z3);
    cudaGetSymbolAddress(&q,   g_q);
    cudaGetSymbolAddress(&y1,  g_y1);
    cudaGetSymbolAddress(&y2,  g_y2);
    cudaGetSymbolAddress(&pw1, g_pw_e1);
    cudaGetSymbolAddress(&pw2, g_pw_e2);
    cudaGetSymbolAddress(&pw3, g_pw_e3);
    cudaGetSymbolAddress(&pw4, g_pw_d1);
    cudaGetSymbolAddress(&pw5, g_pw_d2);
    cudaGetSymbolAddress(&pw6, g_pw_d3);
    cudaGetSymbolAddress(&part, g_part);

    // ---- weight packing (tiny)
    pack_weights<<<(20 * 64 * 72 + 255) / 256, 256>>>(e1w, (u64*)pw1, 156, 128, 64, 0);
    pack_weights<<<(16 * 32 * 72 + 255) / 256, 256>>>(e2w, (u64*)pw2, 128,  64, 32, 0);
    pack_weights<<<( 8 *  8 * 72 + 255) / 256, 256>>>(e3w, (u64*)pw3,  64,   8,  8, 0);
    pack_weights<<<( 1 * 32 * 72 + 255) / 256, 256>>>(d1w, (u64*)pw4,   8,  64, 32, 1);
    pack_weights<<<( 8 * 64 * 72 + 255) / 256, 256>>>(d2w, (u64*)pw5,  64, 128, 64, 1);
    pack_weights<<<(16 * 80 * 72 + 255) / 256, 256>>>(d3w, (u64*)pw6, 128, 156, 80, 1);

    // dynamic smem sizes: input 2*8*4*140*4 = 35840; weights 2*NCPG*72*8
    const int SM64 = 35840 + 2 * 32 * 72 * 8;  // 72704
    const int SM32 = 35840 + 2 * 16 * 72 * 8;  // 54272
    const int SM16 = 35840 + 2 *  8 * 72 * 8;  // 45056

    cudaFuncSetAttribute((const void*)conv3x3p<156, 128, 64, 1, 0, 64>,
                         cudaFuncAttributeMaxDynamicSharedMemorySize, SM64);
    cudaFuncSetAttribute((const void*)conv3x3p<128, 64, 64, 1, 0, 32>,
                         cudaFuncAttributeMaxDynamicSharedMemorySize, SM64);
    cudaFuncSetAttribute((const void*)conv3x3p<64, 8, 16, 1, 0, 8>,
                         cudaFuncAttributeMaxDynamicSharedMemorySize, SM16);
    cudaFuncSetAttribute((const void*)conv3x3p<8, 64, 64, 1, 0, 32>,
                         cudaFuncAttributeMaxDynamicSharedMemorySize, SM64);
    cudaFuncSetAttribute((const void*)conv3x3p<64, 128, 64, 1, 0, 64>,
                         cudaFuncAttributeMaxDynamicSharedMemorySize, SM64);
    cudaFuncSetAttribute((const void*)conv3x3p<128, 156, 64, 2, 0, 80>,
                         cudaFuncAttributeMaxDynamicSharedMemorySize, SM64);
    cudaFuncSetAttribute((const void*)conv3x3p<128, 156, 32, 2, 128, 80>,
                         cudaFuncAttributeMaxDynamicSharedMemorySize, SM32);

    // encoder
    conv3x3p<156, 128, 64, 1, 0, 64><<<dim3(64, 2, 16), 256, SM64>>>(x, (u64*)pw1, e1b, (float*)z1);
    conv3x3p<128,  64, 64, 1, 0, 32><<<dim3(64, 1, 16), 256, SM64>>>((float*)z1, (u64*)pw2, e2b, (float*)z2);
    conv3x3p< 64,   8, 16, 1, 0,  8><<<dim3(64, 1, 16), 256, SM16>>>((float*)z2, (u64*)pw3, e3b, (float*)z3);

    // vector quantizer + loss partials
    vq_kernel<<<256, 256>>>((const float*)z3, emb, (float*)q, (double*)part);

    // decoder
    conv3x3p<  8,  64, 64, 1, 0, 32><<<dim3(64, 1, 16), 256, SM64>>>((float*)q,  (u64*)pw4, d1b, (float*)y1);
    conv3x3p< 64, 128, 64, 1, 0, 64><<<dim3(64, 2, 16), 256, SM64>>>((float*)y1, (u64*)pw5, d2b, (float*)y2);
    conv3x3p<128, 156, 64, 2, 0,   80><<<dim3(64, 2, 16), 256, SM64>>>((float*)y2, (u64*)pw6, d3b, out);
    conv3x3p<128, 156, 32, 2, 128, 80><<<dim3(64, 1, 16), 256, SM32>>>((float*)y2, (u64*)pw6, d3b, out);

    finalize_loss<<<1, 256>>>((const double*)part, out + (out_size - 1));
}

// round 5
// speedup vs baseline: 1.4177x; 1.4177x over previous
#include <cuda_runtime.h>
#include <math.h>

// ---------------------------------------------------------------------------
// VQ-VAE forward.  B=16, L=156, P=8, H=W=128, codebook 512x8.
// R4: back to LDG+STS staging (cp.async regressed: <32 ops/thread + L1 bypass),
//     pre-packed paired weights kept, 1-row blocks (16 accs/thread) for
//     3 CTAs/SM occupancy.
// ---------------------------------------------------------------------------

#define BATCH 16
#define HW    16384   // 128*128

typedef unsigned long long u64;

__device__ __forceinline__ u64 pack2(float lo, float hi) {
    u64 r; asm("mov.b64 %0, {%1, %2};" : "=l"(r) : "f"(lo), "f"(hi)); return r;
}
__device__ __forceinline__ void fma2(u64 &d, u64 a, u64 b) {
    asm("fma.rn.f32x2 %0, %1, %2, %0;" : "+l"(d) : "l"(a), "l"(b));
}
__device__ __forceinline__ float2 unpk(u64 v) {
    float lo, hi; asm("mov.b64 {%0, %1}, %2;" : "=f"(lo), "=f"(hi) : "l"(v));
    return make_float2(lo, hi);
}

// Static device scratch (allocation-free rule).
__device__ float g_z1[BATCH * 128 * HW];
__device__ float g_z2[BATCH *  64 * HW];
__device__ float g_z3[BATCH *   8 * HW];
__device__ float g_q [BATCH *   8 * HW];
__device__ float g_y1[BATCH *  64 * HW];
__device__ float g_y2[BATCH * 128 * HW];
// packed paired weights: [chunk][cp][kc*9+tap] u64 {w[2cp], w[2cp+1]}
__device__ u64 g_pw_e1[20 * 64 * 72];
__device__ u64 g_pw_e2[16 * 32 * 72];
__device__ u64 g_pw_e3[ 8 *  8 * 72];
__device__ u64 g_pw_d1[ 1 * 32 * 72];
__device__ u64 g_pw_d2[ 8 * 64 * 72];
__device__ u64 g_pw_d3[16 * 80 * 72];
__device__ double g_part[256];

// ---------------------------------------------------------------------------
// Pack weights into [chunk][cp][kc*9+tap] u64 pairs.  transposed=1 handles
// ConvTranspose (in,out,kh,kw) with spatial flip: tap' = 8 - tap.
// ---------------------------------------------------------------------------
__global__ void pack_weights(const float* __restrict__ w, u64* __restrict__ pw,
                             int CIN, int COUT, int CP_PAD, int transposed) {
    int idx = blockIdx.x * 256 + threadIdx.x;
    int CHUNKS = (CIN + 7) / 8;
    int total = CHUNKS * CP_PAD * 72;
    if (idx >= total) return;
    int chunk = idx / (CP_PAD * 72);
    int rem   = idx % (CP_PAD * 72);
    int cp    = rem / 72;
    int rem2  = rem % 72;
    int kc    = rem2 / 9;
    int tap   = rem2 % 9;
    int ci    = chunk * 8 + kc;
    int co0 = 2 * cp, co1 = 2 * cp + 1;
    float v0 = 0.f, v1 = 0.f;
    if (ci < CIN) {
        if (transposed) {
            if (co0 < COUT) v0 = w[((size_t)ci * COUT + co0) * 9 + (8 - tap)];
            if (co1 < COUT) v1 = w[((size_t)ci * COUT + co1) * 9 + (8 - tap)];
        } else {
            if (co0 < COUT) v0 = w[((size_t)co0 * CIN + ci) * 9 + tap];
            if (co1 < COUT) v1 = w[((size_t)co1 * CIN + ci) * 9 + tap];
        }
    }
    pw[idx] = pack2(v0, v1);
}

__device__ __forceinline__ float apply_act(float v, int ACT) {
    if (ACT == 1) return fmaxf(v, 0.f);
    if (ACT == 2) return 1.f / (1.f + __expf(-v));
    return v;
}

// ---------------------------------------------------------------------------
// Packed-f32x2 3x3 same-conv.  Block = (n, output row h, MT co at CO_OFF+by*MT).
// 256 thr: lane -> 4 consecutive px (p0=4*lane), cg=tid>>5 -> co-pair group.
// Accumulator f32x2 lanes carry (co, co+1).  16 u64 accs/thread -> low regs,
// 3 CTAs/SM.  smem input row: x[gc] at float idx gc+4; halos idx 3 & 132
// pre-zeroed once and never overwritten.
// ---------------------------------------------------------------------------
template<int CIN, int COUT, int MT, int ACT, int CO_OFF, int CP_PAD>
__global__ __launch_bounds__(256, 3)
void conv3x3r(const float* __restrict__ in, const u64* __restrict__ pw,
              const float* __restrict__ bias, float* __restrict__ out) {
    constexpr int KC     = 8;
    constexpr int NCP    = MT / 16;           // co-pairs per thread
    constexpr int NCPG   = MT / 2;            // co-pairs per block
    constexpr int CHUNKS = (CIN + KC - 1) / KC;
    constexpr int ROWSTR = 136;

    __shared__ float s_in[KC * 3 * ROWSTR];
    __shared__ u64   s_w[NCPG * 72];

    const int n       = blockIdx.z;
    const int h       = blockIdx.x;
    const int co_base = CO_OFF + blockIdx.y * MT;
    const int cp_base = co_base / 2;
    const int tid     = threadIdx.x;
    const int lane    = tid & 31;
    const int cg      = tid >> 5;
    const int p0      = lane * 4;

    const float* inN = in + (size_t)n * CIN * HW;

    // zero halo columns (written once, never overwritten by staging)
    if (tid < KC * 3) {
        float* row = s_in + tid * ROWSTR;
        row[0] = 0.f; row[1] = 0.f; row[2] = 0.f; row[3] = 0.f;
        row[132] = 0.f; row[133] = 0.f; row[134] = 0.f; row[135] = 0.f;
    }

    u64 acc[NCP][4];
#pragma unroll
    for (int c = 0; c < NCP; c++)
#pragma unroll
        for (int k = 0; k < 4; k++) acc[c][k] = 0ull;

    for (int chunk = 0; chunk < CHUNKS; chunk++) {
        // ---- stage input: KC ch x 3 rows x 32 float4
        for (int s4 = tid; s4 < KC * 3 * 32; s4 += 256) {
            int kc = s4 / 96;
            int r  = (s4 / 32) % 3;
            int s  = s4 & 31;
            int ci = chunk * KC + kc;
            int gh = h - 1 + r;
            float4 v = make_float4(0.f, 0.f, 0.f, 0.f);
            if (ci < CIN && gh >= 0 && gh < 128)
                v = *(const float4*)(inN + (size_t)ci * HW + gh * 128 + s * 4);
            *(float4*)(s_in + (kc * 3 + r) * ROWSTR + 4 + s * 4) = v;
        }
        // ---- stage weights: NCPG*72 u64 contiguous (L1-cached LDG)
        {
            const float4* wsrc = (const float4*)(pw + ((size_t)chunk * CP_PAD + cp_base) * 72);
            float4* wdst = (float4*)s_w;
            for (int s = tid; s < NCPG * 36; s += 256) wdst[s] = wsrc[s];
        }
        __syncthreads();

        for (int kc = 0; kc < KC; kc++) {
#pragma unroll
            for (int dh = 0; dh < 3; dh++) {
                const float* row = s_in + (kc * 3 + dh) * ROWSTR;
                float4 A = *(const float4*)(row + p0);
                float4 B = *(const float4*)(row + p0 + 4);
                float4 C = *(const float4*)(row + p0 + 8);
                u64 dup[6];
                dup[0] = pack2(A.w, A.w);
                dup[1] = pack2(B.x, B.x);
                dup[2] = pack2(B.y, B.y);
                dup[3] = pack2(B.z, B.z);
                dup[4] = pack2(B.w, B.w);
                dup[5] = pack2(C.x, C.x);
#pragma unroll
                for (int dw = 0; dw < 3; dw++) {
#pragma unroll
                    for (int cp = 0; cp < NCP; cp++) {
                        u64 w = s_w[(cg * NCP + cp) * 72 + kc * 9 + dh * 3 + dw];
#pragma unroll
                        for (int k = 0; k < 4; k++)
                            fma2(acc[cp][k], w, dup[k + dw]);
                    }
                }
            }
        }
        __syncthreads();
    }

    // ---- epilogue: unpack, bias, activation, vectorized stores
#pragma unroll
    for (int cp = 0; cp < NCP; cp++) {
        int co0 = co_base + 2 * (cg * NCP + cp);
        float2 r0 = unpk(acc[cp][0]);
        float2 r1 = unpk(acc[cp][1]);
        float2 r2 = unpk(acc[cp][2]);
        float2 r3 = unpk(acc[cp][3]);
        size_t rowoff = (size_t)h * 128 + p0;
        if (co0 < COUT) {
            float b = bias[co0];
            float4 o;
            o.x = apply_act(r0.x + b, ACT);
            o.y = apply_act(r1.x + b, ACT);
            o.z = apply_act(r2.x + b, ACT);
            o.w = apply_act(r3.x + b, ACT);
            *(float4*)&out[((size_t)n * COUT + co0) * HW + rowoff] = o;
        }
        if (co0 + 1 < COUT) {
            float b = bias[co0 + 1];
            float4 o;
            o.x = apply_act(r0.y + b, ACT);
            o.y = apply_act(r1.y + b, ACT);
            o.z = apply_act(r2.y + b, ACT);
            o.w = apply_act(r3.y + b, ACT);
            *(float4*)&out[((size_t)n * COUT + (co0 + 1)) * HW + rowoff] = o;
        }
    }
}

// ---------------------------------------------------------------------------
// Vector quantizer (groups of 8 along W, torch .view semantics).
// ---------------------------------------------------------------------------
__global__ __launch_bounds__(256)
void vq_kernel(const float* __restrict__ z, const float* __restrict__ emb,
               float* __restrict__ q, double* __restrict__ part) {
    __shared__ float  s_e[512 * 8];
    __shared__ float  s_hn[512];
    __shared__ double s_red[256];

    const int tid = threadIdx.x;
    for (int i = tid; i < 4096; i += 256) s_e[i] = emb[i];
    __syncthreads();
    for (int k = tid; k < 512; k += 256) {
        float s = 0.f;
#pragma unroll
        for (int j = 0; j < 8; j++) { float e = s_e[k * 8 + j]; s += e * e; }
        s_hn[k] = 0.5f * s;
    }
    __syncthreads();

    const int base = blockIdx.x * 1024 + tid;
    float v[4][8];
#pragma unroll
    for (int u = 0; u < 4; u++) {
        int vi = base + u * 256;
        float4 a = ((const float4*)z)[vi * 2];
        float4 b = ((const float4*)z)[vi * 2 + 1];
        v[u][0] = a.x; v[u][1] = a.y; v[u][2] = a.z; v[u][3] = a.w;
        v[u][4] = b.x; v[u][5] = b.y; v[u][6] = b.z; v[u][7] = b.w;
    }

    float best[4] = {3.4e38f, 3.4e38f, 3.4e38f, 3.4e38f};
    int   bk[4]   = {0, 0, 0, 0};
    for (int k = 0; k < 512; k++) {
        float e0 = s_e[k * 8 + 0], e1 = s_e[k * 8 + 1], e2 = s_e[k * 8 + 2], e3 = s_e[k * 8 + 3];
        float e4 = s_e[k * 8 + 4], e5 = s_e[k * 8 + 5], e6 = s_e[k * 8 + 6], e7 = s_e[k * 8 + 7];
        float hn = s_hn[k];
#pragma unroll
        for (int u = 0; u < 4; u++) {
            float dot = e0 * v[u][0] + e1 * v[u][1] + e2 * v[u][2] + e3 * v[u][3]
                      + e4 * v[u][4] + e5 * v[u][5] + e6 * v[u][6] + e7 * v[u][7];
            float sc = hn - dot;
            if (sc < best[u]) { best[u] = sc; bk[u] = k; }
        }
    }

    float sq = 0.f;
#pragma unroll
    for (int u = 0; u < 4; u++) {
        int vi = base + u * 256;
        int kb = bk[u];
        float4 o1, o2;
        o1.x = s_e[kb * 8 + 0]; o1.y = s_e[kb * 8 + 1];
        o1.z = s_e[kb * 8 + 2]; o1.w = s_e[kb * 8 + 3];
        o2.x = s_e[kb * 8 + 4]; o2.y = s_e[kb * 8 + 5];
        o2.z = s_e[kb * 8 + 6]; o2.w = s_e[kb * 8 + 7];
#pragma unroll
        for (int j = 0; j < 8; j++) {
            float d = s_e[kb * 8 + j] - v[u][j];
            sq += d * d;
        }
        ((float4*)q)[vi * 2]     = o1;
        ((float4*)q)[vi * 2 + 1] = o2;
    }

    s_red[tid] = (double)sq;
    __syncthreads();
    for (int o = 128; o > 0; o >>= 1) {
        if (tid < o) s_red[tid] += s_red[tid + o];
        __syncthreads();
    }
    if (tid == 0) part[blockIdx.x] = s_red[0];
}

__global__ void finalize_loss(const double* __restrict__ part, float* __restrict__ outp) {
    __shared__ double s[256];
    int tid = threadIdx.x;
    s[tid] = part[tid];
    __syncthreads();
    for (int o = 128; o > 0; o >>= 1) {
        if (tid < o) s[tid] += s[tid + o];
        __syncthreads();
    }
    if (tid == 0) *outp = (float)(1.25 * s[0] / 2097152.0);
}

// ---------------------------------------------------------------------------
extern "C" void kernel_launch(void* const* d_in, const int* in_sizes, int n_in,
                              void* d_out, int out_size) {
    (void)in_sizes; (void)n_in;
    const float* x   = (const float*)d_in[0];
    const float* e1w = (const float*)d_in[1];
    const float* e1b = (const float*)d_in[2];
    const float* e2w = (const float*)d_in[3];
    const float* e2b = (const float*)d_in[4];
    const float* e3w = (const float*)d_in[5];
    const float* e3b = (const float*)d_in[6];
    const float* emb = (const float*)d_in[7];
    const float* d1w = (const float*)d_in[8];
    const float* d1b = (const float*)d_in[9];
    const float* d2w = (const float*)d_in[10];
    const float* d2b = (const float*)d_in[11];
    const float* d3w = (const float*)d_in[12];
    const float* d3b = (const float*)d_in[13];
    float* out = (float*)d_out;

    void *z1, *z2, *z3, *q, *y1, *y2, *part;
    void *pw1, *pw2, *pw3, *pw4, *pw5, *pw6;
    cudaGetSymbolAddress(&z1,  g_z1);
    cudaGetSymbolAddress(&z2,  g_z2);
    cudaGetSymbolAddress(&z3,  g_z3);
    cudaGetSymbolAddress(&q,   g_q);
    cudaGetSymbolAddress(&y1,  g_y1);
    cudaGetSymbolAddress(&y2,  g_y2);
    cudaGetSymbolAddress(&pw1, g_pw_e1);
    cudaGetSymbolAddress(&pw2, g_pw_e2);
    cudaGetSymbolAddress(&pw3, g_pw_e3);
    cudaGetSymbolAddress(&pw4, g_pw_d1);
    cudaGetSymbolAddress(&pw5, g_pw_d2);
    cudaGetSymbolAddress(&pw6, g_pw_d3);
    cudaGetSymbolAddress(&part, g_part);

    // ---- weight packing (tiny)
    pack_weights<<<(20 * 64 * 72 + 255) / 256, 256>>>(e1w, (u64*)pw1, 156, 128, 64, 0);
    pack_weights<<<(16 * 32 * 72 + 255) / 256, 256>>>(e2w, (u64*)pw2, 128,  64, 32, 0);
    pack_weights<<<( 8 *  8 * 72 + 255) / 256, 256>>>(e3w, (u64*)pw3,  64,   8,  8, 0);
    pack_weights<<<( 1 * 32 * 72 + 255) / 256, 256>>>(d1w, (u64*)pw4,   8,  64, 32, 1);
    pack_weights<<<( 8 * 64 * 72 + 255) / 256, 256>>>(d2w, (u64*)pw5,  64, 128, 64, 1);
    pack_weights<<<(16 * 80 * 72 + 255) / 256, 256>>>(d3w, (u64*)pw6, 128, 156, 80, 1);

    // encoder
    conv3x3r<156, 128, 64, 1, 0, 64><<<dim3(128, 2, 16), 256>>>(x, (u64*)pw1, e1b, (float*)z1);
    conv3x3r<128,  64, 64, 1, 0, 32><<<dim3(128, 1, 16), 256>>>((float*)z1, (u64*)pw2, e2b, (float*)z2);
    conv3x3r< 64,   8, 16, 1, 0,  8><<<dim3(128, 1, 16), 256>>>((float*)z2, (u64*)pw3, e3b, (float*)z3);

    // vector quantizer + loss partials
    vq_kernel<<<256, 256>>>((const float*)z3, emb, (float*)q, (double*)part);

    // decoder
    conv3x3r<  8,  64, 64, 1, 0, 32><<<dim3(128, 1, 16), 256>>>((float*)q,  (u64*)pw4, d1b, (float*)y1);
    conv3x3r< 64, 128, 64, 1, 0, 64><<<dim3(128, 2, 16), 256>>>((float*)y1, (u64*)pw5, d2b, (float*)y2);
    conv3x3r<128, 156, 64, 2, 0,   80><<<dim3(128, 2, 16), 256>>>((float*)y2, (u64*)pw6, d3b, out);
    conv3x3r<128, 156, 32, 2, 128, 80><<<dim3(128, 1, 16), 256>>>((float*)y2, (u64*)pw6, d3b, out);

    finalize_loss<<<1, 256>>>((const double*)part, out + (out_size - 1));
}